// round 3
// baseline (speedup 1.0000x reference)
#include <cuda_runtime.h>
#include <math.h>

#define G_      256
#define NATOMS  32
#define DD      41
#define NRAD    4
#define NCOEF   16
#define NOUT    64
#define TPB     192
#define BPA     18              // blocks per atom: ceil(2*41*41/192)
#define UNITS   (2 * DD * DD)   // 3362 half-lines per atom

typedef unsigned long long u64;

__device__ __forceinline__ u64 pack2(float lo, float hi) {
    u64 r; asm("mov.b64 %0, {%1,%2};" : "=l"(r) : "f"(lo), "f"(hi)); return r;
}
__device__ __forceinline__ void unpack2(u64 p, float& lo, float& hi) {
    asm("mov.b64 {%0,%1}, %2;" : "=f"(lo), "=f"(hi) : "l"(p));
}
__device__ __forceinline__ void fma2(u64& d, u64 a, u64 b) {
    asm("fma.rn.f32x2 %0, %1, %2, %0;" : "+l"(d) : "l"(a), "l"(b));
}
__device__ __forceinline__ u64 add2(u64 a, u64 b) {
    u64 r; asm("add.rn.f32x2 %0, %1, %2;" : "=l"(r) : "l"(a), "l"(b)); return r;
}

__global__ void zero_kernel(float* out, int n) {
    int i = blockIdx.x * blockDim.x + threadIdx.x;
    if (i < n) out[i] = 0.0f;
}

__launch_bounds__(TPB, 3)
__global__ void project_kernel(const float* __restrict__ rho,
                               const float* __restrict__ positions,
                               const float* __restrict__ Wmat,
                               const int*   __restrict__ offs,
                               float*       __restrict__ out)
{
    const int atom = blockIdx.x / BPA;
    const int ub   = blockIdx.x % BPA;
    const int t    = threadIdx.x;
    const int unit = ub * TPB + t;

    __shared__ float red[NOUT];
    if (t < NOUT) red[t] = 0.0f;
    __syncthreads();

    u64 acc2[NRAD][NCOEF / 2];
    #pragma unroll
    for (int a = 0; a < NRAD; a++)
        #pragma unroll
        for (int h = 0; h < NCOEF / 2; h++) acc2[a][h] = 0ull;

    if (unit < UNITS) {
        const float Af = 0.1f;
        const int half = unit & 1;
        const int line = unit >> 1;
        const int i = line / DD;
        const int j = line - i * DD;

        // per-atom position -> cm, dr (matches R<=2 passing kernels' math)
        float px = __ldg(positions + atom * 3 + 0);
        float py = __ldg(positions + atom * 3 + 1);
        float pz = __ldg(positions + atom * 3 + 2);
        float cmfx = rintf(px / Af), cmfy = rintf(py / Af), cmfz = rintf(pz / Af);
        float drx = px - Af * cmfx, dry = py - Af * cmfy, drz = pz - Af * cmfz;
        int cmx = (int)cmfx, cmy = (int)cmfy, cmz = (int)cmfz;

        float X = fmaf(Af, (float)(i - 20), -drx);
        float Y = fmaf(Af, (float)(j - 20), -dry);
        float rho2 = fmaf(X, X, Y * Y);
        float h2 = 4.0f - rho2;

        if (h2 > 0.0f) {
            float hw = sqrtf(h2);
            int smin = max(-20, (int)ceilf((drz - hw) * 10.0f) - 1);
            int smax = min(20, (int)floorf((drz + hw) * 10.0f) + 1);
            int sc = (int)floorf(drz * 10.0f);
            int s0, s1;
            if (half == 0) { s0 = smin;             s1 = min(sc, smax); }
            else           { s0 = max(sc + 1, smin); s1 = smax;          }

            const int ixy = (((cmx + i - 20) & 255) << 16)
                          | (((cmy + j - 20) & 255) << 8);

            // line-invariant pieces of Y_lm
            float XY = X * Y;
            float X2 = X * X, Y2 = Y * Y;

            #pragma unroll 2
            for (int s = s0; s <= s1; s++) {
                float Z = fmaf(Af, (float)s, -drz);
                int addr = ixy + ((cmz + s) & 255);
                float srho = __ldg(rho + addr);
                float r2 = fmaf(Z, Z, rho2);
                srho = (r2 < 4.0f) ? srho : 0.0f;      // exact reference cutoff guard
                float rinv = (r2 > 1e-30f) ? rsqrtf(r2) : 0.0f;
                float R = r2 * rinv;

                float tt = 2.0f - R;
                float g0 = r2 * tt * tt;
                float g1 = g0 * tt, g2 = g1 * tt, g3 = g2 * tt;

                float u_ = X * rinv, v_ = Y * rinv, w_ = Z * rinv;
                float u2 = u_ * u_, v2 = v_ * v_, w2 = w_ * w_;
                float uv = u_ * v_;
                float f5w1 = fmaf(5.0f, w2, -1.0f);
                float umv = u2 - v2;

                float Yv[NCOEF];
                Yv[0]  = 0.28209479177387814f;
                Yv[1]  = 0.48860251190291992f * v_;
                Yv[2]  = 0.48860251190291992f * w_;
                Yv[3]  = 0.48860251190291992f * u_;
                Yv[4]  = 1.09254843059207907f * uv;
                Yv[5]  = 1.09254843059207907f * (v_ * w_);
                Yv[6]  = 0.31539156525252005f * fmaf(3.0f, w2, -1.0f);
                Yv[7]  = 1.09254843059207907f * (u_ * w_);
                Yv[8]  = 0.54627421529603959f * umv;
                Yv[9]  = 0.59004358992664352f * (v_ * fmaf(3.0f, u2, -v2));
                Yv[10] = 2.89061144264055405f * (uv * w_);
                Yv[11] = 0.45704579946446577f * (v_ * f5w1);
                Yv[12] = 0.37317633259011546f * (w_ * fmaf(5.0f, w2, -3.0f));
                Yv[13] = 0.45704579946446577f * (u_ * f5w1);
                Yv[14] = 1.44530572132027735f * (w_ * umv);
                Yv[15] = 0.59004358992664352f * (u_ * fmaf(u2, 1.0f, -3.0f * v2));

                u64 Ypk[NCOEF / 2];
                #pragma unroll
                for (int hh = 0; hh < NCOEF / 2; hh++)
                    Ypk[hh] = pack2(Yv[2 * hh], Yv[2 * hh + 1]);

                float gr0 = g0 * srho, gr1 = g1 * srho;
                float gr2 = g2 * srho, gr3 = g3 * srho;
                u64 gp0 = pack2(gr0, gr0), gp1 = pack2(gr1, gr1);
                u64 gp2 = pack2(gr2, gr2), gp3 = pack2(gr3, gr3);

                #pragma unroll
                for (int hh = 0; hh < NCOEF / 2; hh++) {
                    fma2(acc2[0][hh], gp0, Ypk[hh]);
                    fma2(acc2[1][hh], gp1, Ypk[hh]);
                    fma2(acc2[2][hh], gp2, Ypk[hh]);
                    fma2(acc2[3][hh], gp3, Ypk[hh]);
                }
            }
        }
    }

    // Block reduction: packed warp butterfly -> shared atomics
    #pragma unroll
    for (int a = 0; a < NRAD; a++) {
        #pragma unroll
        for (int h = 0; h < NCOEF / 2; h++) {
            u64 v = acc2[a][h];
            #pragma unroll
            for (int o = 16; o > 0; o >>= 1)
                v = add2(v, __shfl_down_sync(0xffffffffu, v, o));
            if ((t & 31) == 0) {
                float lo, hi;
                unpack2(v, lo, hi);
                atomicAdd(&red[a * NCOEF + 2 * h],     lo);
                atomicAdd(&red[a * NCOEF + 2 * h + 1], hi);
            }
        }
    }
    __syncthreads();

    // Final mix: out[n][c] = V_CELL * sum_a W[n][a] * (1/Nn_a) * M[a][c]
    if (t < NOUT) {
        int n = t >> 4, c = t & 15;
        const double dens[4]  = {1474560.0, 5898240.0, 23592960.0, 94371840.0};
        const double prods[4] = {1663200.0, 8648640.0, 32432400.0, 98017920.0};
        const double Ad = 25.6 / 256.0;
        const float vcell = (float)(Ad * Ad * Ad);
        float sum = 0.0f;
        #pragma unroll
        for (int a = 0; a < NRAD; a++) {
            float invNn = (float)sqrt(prods[a] / dens[a]);
            sum += Wmat[n * 4 + a] * invNn * red[a * NCOEF + c];
        }
        atomicAdd(&out[atom * NOUT + t], sum * vcell);
    }
}

extern "C" void kernel_launch(void* const* d_in, const int* in_sizes, int n_in,
                              void* d_out, int out_size) {
    const float* rho  = (const float*)d_in[0];
    const float* pos  = (const float*)d_in[1];
    const float* W    = (const float*)d_in[2];
    const int*   offs = (const int*)d_in[3];
    float* out = (float*)d_out;

    zero_kernel<<<(NATOMS * NOUT + 255) / 256, 256>>>(out, NATOMS * NOUT);
    project_kernel<<<NATOMS * BPA, TPB>>>(rho, pos, W, offs, out);
}

// round 4
// speedup vs baseline: 1.1974x; 1.1974x over previous
#include <cuda_runtime.h>
#include <math.h>

#define G_      256
#define NATOMS  32
#define DD      41
#define NRAD    4
#define NCOEF   16
#define NOUT    64
#define TPB     256
#define BPA     9               // blocks per atom
#define WPA     (BPA * (TPB/32))// 72 warps per atom
#define NLINES  (DD * DD)       // 1681

typedef unsigned long long u64;

__device__ __forceinline__ u64 pack2(float lo, float hi) {
    u64 r; asm("mov.b64 %0, {%1,%2};" : "=l"(r) : "f"(lo), "f"(hi)); return r;
}
__device__ __forceinline__ void unpack2(u64 p, float& lo, float& hi) {
    asm("mov.b64 {%0,%1}, %2;" : "=f"(lo), "=f"(hi) : "l"(p));
}
__device__ __forceinline__ void fma2(u64& d, u64 a, u64 b) {
    asm("fma.rn.f32x2 %0, %1, %2, %0;" : "+l"(d) : "l"(a), "l"(b));
}
__device__ __forceinline__ u64 add2(u64 a, u64 b) {
    u64 r; asm("add.rn.f32x2 %0, %1, %2;" : "=l"(r) : "l"(a), "l"(b)); return r;
}

__global__ void zero_kernel(float* out, int n) {
    int i = blockIdx.x * blockDim.x + threadIdx.x;
    if (i < n) out[i] = 0.0f;
}

__launch_bounds__(TPB, 2)
__global__ void project_kernel(const float* __restrict__ rho,
                               const float* __restrict__ positions,
                               const float* __restrict__ Wmat,
                               const int*   __restrict__ offs,
                               float*       __restrict__ out)
{
    const int atom = blockIdx.x / BPA;
    const int ub   = blockIdx.x % BPA;
    const int t    = threadIdx.x;
    const int lane = t & 31;
    const int wg   = (ub << 3) + (t >> 5);      // warp id within atom: 0..71

    __shared__ float red[NOUT];
    if (t < NOUT) red[t] = 0.0f;
    __syncthreads();

    // per-atom setup (uniform)
    const float Af = 0.1f;
    float px = __ldg(positions + atom * 3 + 0);
    float py = __ldg(positions + atom * 3 + 1);
    float pz = __ldg(positions + atom * 3 + 2);
    float cmfx = rintf(px / Af), cmfy = rintf(py / Af), cmfz = rintf(pz / Af);
    float drx = px - Af * cmfx, dry = py - Af * cmfy, drz = pz - Af * cmfz;
    int cmx = (int)cmfx, cmy = (int)cmfy, cmz = (int)cmfz;

    u64 acc2[NRAD][NCOEF / 2];
    #pragma unroll
    for (int a = 0; a < NRAD; a++)
        #pragma unroll
        for (int h = 0; h < NCOEF / 2; h++) acc2[a][h] = 0ull;

    for (int line = wg; line < NLINES; line += WPA) {
        int i = line / DD;
        int j = line - i * DD;
        float X = fmaf(Af, (float)(i - 20), -drx);
        float Y = fmaf(Af, (float)(j - 20), -dry);
        float rho2 = fmaf(X, X, Y * Y);
        float h2 = 4.0f - rho2;
        if (h2 <= 0.0f) continue;                 // warp-uniform skip

        float hw = sqrtf(h2);
        int smin = max(-20, (int)ceilf((drz - hw) * 10.0f) - 1);
        int smax = min(20, (int)floorf((drz + hw) * 10.0f) + 1);
        const int ixy = (((cmx + i - 20) & 255) << 16)
                      | (((cmy + j - 20) & 255) << 8);

        // line-uniform SH prefactors (unnormalized-coordinate form)
        float X2 = X * X, Y2 = Y * Y, XY = X * Y;
        float umv = X2 - Y2;
        float U1  = 0.48860251190291992f * Y;
        float U3  = 0.48860251190291992f * X;
        float U4  = 1.09254843059207907f * XY;
        float U5  = 1.09254843059207907f * Y;
        float U7  = 1.09254843059207907f * X;
        float U8  = 0.54627421529603959f * umv;
        float U9  = 0.59004358992664352f * (Y * fmaf(3.0f, X2, -Y2));
        float U10 = 2.89061144264055405f * XY;
        float U11 = 0.45704579946446577f * Y;
        float U13 = 0.45704579946446577f * X;
        float U14 = 1.44530572132027735f * umv;
        float U15 = 0.59004358992664352f * (X * fmaf(-3.0f, Y2, X2));

        for (int sb = smin; sb <= smax; sb += 32) {   // 1-2 uniform passes
            int s = sb + lane;
            float Z = fmaf(Af, (float)s, -drz);
            int addr = ixy | ((cmz + s) & 255);
            float srho = __ldg(rho + addr);
            float r2 = fmaf(Z, Z, rho2);
            srho = (s <= smax && r2 < 4.0f) ? srho : 0.0f;   // branch-free mask

            float rinv = (r2 > 1e-30f) ? rsqrtf(r2) : 0.0f;
            float R = r2 * rinv;
            float tt = 2.0f - R;
            float g0 = r2 * tt * tt;
            float g1 = g0 * tt, g2 = g1 * tt, g3 = g2 * tt;

            float rv2 = rinv * rinv, rv3 = rv2 * rinv;
            float Z2  = Z * Z;
            float f3  = fmaf(3.0f, Z2, -r2);
            float f5  = fmaf(5.0f, Z2, -r2);
            float f53 = fmaf(-2.0f, r2, f5);          // 5Z^2 - 3r^2
            float Zr  = Z * rinv, Zr2 = Z * rv2, Zr3 = Z * rv3;
            float f5r = f5 * rv3;

            float Yv[NCOEF];
            Yv[0]  = 0.28209479177387814f;
            Yv[1]  = U1 * rinv;
            Yv[2]  = 0.48860251190291992f * Zr;
            Yv[3]  = U3 * rinv;
            Yv[4]  = U4 * rv2;
            Yv[5]  = U5 * Zr2;
            Yv[6]  = 0.31539156525252005f * (f3 * rv2);
            Yv[7]  = U7 * Zr2;
            Yv[8]  = U8 * rv2;
            Yv[9]  = U9 * rv3;
            Yv[10] = U10 * Zr3;
            Yv[11] = U11 * f5r;
            Yv[12] = 0.37317633259011546f * (f53 * Zr3);
            Yv[13] = U13 * f5r;
            Yv[14] = U14 * Zr3;
            Yv[15] = U15 * rv3;

            u64 Ypk[NCOEF / 2];
            #pragma unroll
            for (int hh = 0; hh < NCOEF / 2; hh++)
                Ypk[hh] = pack2(Yv[2 * hh], Yv[2 * hh + 1]);

            float gr0 = g0 * srho, gr1 = g1 * srho;
            float gr2 = g2 * srho, gr3 = g3 * srho;
            u64 gp0 = pack2(gr0, gr0), gp1 = pack2(gr1, gr1);
            u64 gp2 = pack2(gr2, gr2), gp3 = pack2(gr3, gr3);

            #pragma unroll
            for (int hh = 0; hh < NCOEF / 2; hh++) {
                fma2(acc2[0][hh], gp0, Ypk[hh]);
                fma2(acc2[1][hh], gp1, Ypk[hh]);
                fma2(acc2[2][hh], gp2, Ypk[hh]);
                fma2(acc2[3][hh], gp3, Ypk[hh]);
            }
        }
    }

    // Block reduction: packed warp butterfly -> shared atomics
    #pragma unroll
    for (int a = 0; a < NRAD; a++) {
        #pragma unroll
        for (int h = 0; h < NCOEF / 2; h++) {
            u64 v = acc2[a][h];
            #pragma unroll
            for (int o = 16; o > 0; o >>= 1)
                v = add2(v, __shfl_down_sync(0xffffffffu, v, o));
            if (lane == 0) {
                float lo, hi;
                unpack2(v, lo, hi);
                atomicAdd(&red[a * NCOEF + 2 * h],     lo);
                atomicAdd(&red[a * NCOEF + 2 * h + 1], hi);
            }
        }
    }
    __syncthreads();

    // Final mix: out[n][c] = V_CELL * sum_a W[n][a] * (1/Nn_a) * M[a][c]
    if (t < NOUT) {
        int n = t >> 4, c = t & 15;
        const double dens[4]  = {1474560.0, 5898240.0, 23592960.0, 94371840.0};
        const double prods[4] = {1663200.0, 8648640.0, 32432400.0, 98017920.0};
        const double Ad = 25.6 / 256.0;
        const float vcell = (float)(Ad * Ad * Ad);
        float sum = 0.0f;
        #pragma unroll
        for (int a = 0; a < NRAD; a++) {
            float invNn = (float)sqrt(prods[a] / dens[a]);
            sum += Wmat[n * 4 + a] * invNn * red[a * NCOEF + c];
        }
        atomicAdd(&out[atom * NOUT + t], sum * vcell);
    }
}

extern "C" void kernel_launch(void* const* d_in, const int* in_sizes, int n_in,
                              void* d_out, int out_size) {
    const float* rho  = (const float*)d_in[0];
    const float* pos  = (const float*)d_in[1];
    const float* W    = (const float*)d_in[2];
    const int*   offs = (const int*)d_in[3];
    float* out = (float*)d_out;

    zero_kernel<<<(NATOMS * NOUT + 255) / 256, 256>>>(out, NATOMS * NOUT);
    project_kernel<<<NATOMS * BPA, TPB>>>(rho, pos, W, offs, out);
}

// round 5
// speedup vs baseline: 1.2942x; 1.0808x over previous
#include <cuda_runtime.h>
#include <math.h>

#define G_      256
#define NATOMS  32
#define DD      41
#define NRAD    4
#define NCOEF   16
#define NOUT    64
#define TPB     128
#define UNR     4
#define BPA     18
#define NP      (DD * DD * DD)                    // 68921
#define TILE    (TPB * UNR)                       // 512
#define NTILES  ((NP + TILE - 1) / TILE)          // 135

typedef unsigned long long u64;

__device__ __forceinline__ u64 pack2(float lo, float hi) {
    u64 r; asm("mov.b64 %0, {%1,%2};" : "=l"(r) : "f"(lo), "f"(hi)); return r;
}
__device__ __forceinline__ void unpack2(u64 p, float& lo, float& hi) {
    asm("mov.b64 {%0,%1}, %2;" : "=f"(lo), "=f"(hi) : "l"(p));
}
__device__ __forceinline__ void fma2(u64& d, u64 a, u64 b) {
    asm("fma.rn.f32x2 %0, %1, %2, %0;" : "+l"(d) : "l"(a), "l"(b));
}
__device__ __forceinline__ u64 add2(u64 a, u64 b) {
    u64 r; asm("add.rn.f32x2 %0, %1, %2;" : "=l"(r) : "l"(a), "l"(b)); return r;
}

__global__ void zero_kernel(float* out, int n) {
    int i = blockIdx.x * blockDim.x + threadIdx.x;
    if (i < n) out[i] = 0.0f;
}

__launch_bounds__(TPB, 5)
__global__ void project_kernel(const float* __restrict__ rho,
                               const float* __restrict__ positions,
                               const float* __restrict__ Wmat,
                               const int*   __restrict__ offs,
                               float*       __restrict__ out)
{
    const int atom = blockIdx.x / BPA;
    const int ub   = blockIdx.x % BPA;
    const int t    = threadIdx.x;

    // .x = coord (A*off - dr), .y = pre-shifted wrapped grid index (as bits)
    __shared__ float2 sX[DD], sY[DD], sZ[DD];
    __shared__ float  red[NOUT];

    if (t < 3 * DD) {
        const float Af = 0.1f;                     // A = 25.6/256 exactly
        int d = t / DD, s = t % DD;
        float p   = __ldg(positions + atom * 3 + d);
        float cmf = rintf(p / Af);                 // round-half-even == jnp.round
        float dr  = p - Af * cmf;
        int   cm  = (int)cmf;
        int   off = __ldg(offs + s);
        float c   = Af * (float)off - dr;
        int   idx = (off + cm) & (G_ - 1);
        if (d == 0)      sX[s] = make_float2(c, __int_as_float(idx << 16));
        else if (d == 1) sY[s] = make_float2(c, __int_as_float(idx << 8));
        else             sZ[s] = make_float2(c, __int_as_float(idx));
    }
    if (t < NOUT) red[t] = 0.0f;
    __syncthreads();

    u64 acc2[NRAD][NCOEF / 2];
    #pragma unroll
    for (int a = 0; a < NRAD; a++)
        #pragma unroll
        for (int h = 0; h < NCOEF / 2; h++) acc2[a][h] = 0ull;

    // Round-robin 512-point tiles across the 18 blocks of this atom (balance).
    for (int tile = ub; tile < NTILES; tile += BPA) {
        const int base = tile * TILE + t;

        u64   pXY[UNR], pZR[UNR];                  // packed (X,Y), (Z,r2)
        float srp[UNR];

        // Phase 1: decode + batched loads (MLP = UNR); srho pre-masked.
        #pragma unroll
        for (int u = 0; u < UNR; u++) {
            int m = base + u * TPB;
            bool inb = m < NP;
            int mm = inb ? m : 0;
            int i = mm / (DD * DD);
            int r = mm - i * (DD * DD);
            int j = r / DD;
            int k = r - j * DD;
            float2 px = sX[i], py = sY[j], pz = sZ[k];
            float X = px.x, Y = py.x, Z = pz.x;
            int addr = __float_as_int(px.y) + __float_as_int(py.y) + __float_as_int(pz.y);
            float r2 = fmaf(X, X, fmaf(Y, Y, Z * Z));
            float v = __ldg(rho + addr);
            srp[u] = (inb && r2 < 4.0f) ? v : 0.0f;   // exact: dead lanes add 0
            pXY[u] = pack2(X, Y);
            pZR[u] = pack2(Z, r2);
        }

        // Phase 2: branch-free heavy body; skip only fully-dead batches.
        #pragma unroll
        for (int u = 0; u < UNR; u++) {
            if (!__any_sync(0xffffffffu, srp[u] != 0.0f)) continue;  // warp-uniform
            float X, Y, Z, r2, srho = srp[u];
            unpack2(pXY[u], X, Y);
            unpack2(pZR[u], Z, r2);

            float rinv = (r2 > 1e-30f) ? rsqrtf(r2) : 0.0f;
            float R = r2 * rinv;
            float tt = 2.0f - R;
            float g0 = r2 * tt * tt;
            float g1 = g0 * tt, g2 = g1 * tt, g3 = g2 * tt;

            float u_ = X * rinv, v_ = Y * rinv, w_ = Z * rinv;
            float u2 = u_ * u_, v2 = v_ * v_, w2 = w_ * w_;
            float uv = u_ * v_;
            float f5w1 = fmaf(5.0f, w2, -1.0f);
            float umv = u2 - v2;

            float Yv[NCOEF];
            Yv[0]  = 0.28209479177387814f;
            Yv[1]  = 0.48860251190291992f * v_;
            Yv[2]  = 0.48860251190291992f * w_;
            Yv[3]  = 0.48860251190291992f * u_;
            Yv[4]  = 1.09254843059207907f * uv;
            Yv[5]  = 1.09254843059207907f * (v_ * w_);
            Yv[6]  = 0.31539156525252005f * fmaf(3.0f, w2, -1.0f);
            Yv[7]  = 1.09254843059207907f * (u_ * w_);
            Yv[8]  = 0.54627421529603959f * umv;
            Yv[9]  = 0.59004358992664352f * (v_ * fmaf(3.0f, u2, -v2));
            Yv[10] = 2.89061144264055405f * (uv * w_);
            Yv[11] = 0.45704579946446577f * (v_ * f5w1);
            Yv[12] = 0.37317633259011546f * (w_ * fmaf(5.0f, w2, -3.0f));
            Yv[13] = 0.45704579946446577f * (u_ * f5w1);
            Yv[14] = 1.44530572132027735f * (w_ * umv);
            Yv[15] = 0.59004358992664352f * (u_ * fmaf(u2, 1.0f, -3.0f * v2));

            u64 Ypk[NCOEF / 2];
            #pragma unroll
            for (int hh = 0; hh < NCOEF / 2; hh++)
                Ypk[hh] = pack2(Yv[2 * hh], Yv[2 * hh + 1]);

            float gr0 = g0 * srho, gr1 = g1 * srho;
            float gr2 = g2 * srho, gr3 = g3 * srho;
            u64 gp0 = pack2(gr0, gr0), gp1 = pack2(gr1, gr1);
            u64 gp2 = pack2(gr2, gr2), gp3 = pack2(gr3, gr3);

            #pragma unroll
            for (int hh = 0; hh < NCOEF / 2; hh++) {
                fma2(acc2[0][hh], gp0, Ypk[hh]);
                fma2(acc2[1][hh], gp1, Ypk[hh]);
                fma2(acc2[2][hh], gp2, Ypk[hh]);
                fma2(acc2[3][hh], gp3, Ypk[hh]);
            }
        }
    }

    // Block reduction: packed warp butterfly -> shared atomics
    #pragma unroll
    for (int a = 0; a < NRAD; a++) {
        #pragma unroll
        for (int h = 0; h < NCOEF / 2; h++) {
            u64 v = acc2[a][h];
            #pragma unroll
            for (int o = 16; o > 0; o >>= 1)
                v = add2(v, __shfl_down_sync(0xffffffffu, v, o));
            if ((t & 31) == 0) {
                float lo, hi;
                unpack2(v, lo, hi);
                atomicAdd(&red[a * NCOEF + 2 * h],     lo);
                atomicAdd(&red[a * NCOEF + 2 * h + 1], hi);
            }
        }
    }
    __syncthreads();

    // Final mix: out[n][c] = V_CELL * sum_a W[n][a] * (1/Nn_a) * M[a][c]
    if (t < NOUT) {
        int n = t >> 4, c = t & 15;
        const double dens[4]  = {1474560.0, 5898240.0, 23592960.0, 94371840.0};
        const double prods[4] = {1663200.0, 8648640.0, 32432400.0, 98017920.0};
        const double Ad = 25.6 / 256.0;
        const float vcell = (float)(Ad * Ad * Ad);
        float sum = 0.0f;
        #pragma unroll
        for (int a = 0; a < NRAD; a++) {
            float invNn = (float)sqrt(prods[a] / dens[a]);
            sum += __ldg(Wmat + n * 4 + a) * invNn * red[a * NCOEF + c];
        }
        atomicAdd(&out[atom * NOUT + t], sum * vcell);
    }
}

extern "C" void kernel_launch(void* const* d_in, const int* in_sizes, int n_in,
                              void* d_out, int out_size) {
    const float* rho  = (const float*)d_in[0];
    const float* pos  = (const float*)d_in[1];
    const float* W    = (const float*)d_in[2];
    const int*   offs = (const int*)d_in[3];
    float* out = (float*)d_out;

    zero_kernel<<<(NATOMS * NOUT + 255) / 256, 256>>>(out, NATOMS * NOUT);
    project_kernel<<<NATOMS * BPA, TPB>>>(rho, pos, W, offs, out);
}